// round 7
// baseline (speedup 1.0000x reference)
#include <cuda_runtime.h>
#include <cuda_bf16.h>
#include <cstdint>
#include <cstddef>

// ---------------------------------------------------------------------------
// CustomBLIP, normalization deferred:
//   raw_img = image_embeds@Wi^T+bi (fp32), raw_txt = text_embeds@Wt^T+bt (bf16)
//   feats[b,k] = relu( S_b * sum_{i,j} raw_img[b,i] raw_txt[b,j] Wp[k,i,j] + bp[k] )
//     where S_b = 1/(max(||raw_img_b||,eps) * max(||raw_txt_b||,eps))
//   out[b] = sigmoid( feats @ Wc^T + bc )
// ---------------------------------------------------------------------------

#define B_SZ   256
#define M_DIM  512

__device__ float          g_img[B_SZ * M_DIM];      // raw, fp32
__device__ __nv_bfloat16  g_txt_bf[B_SZ * M_DIM];   // raw, bf16
__device__ float          g_n2[2 * 8 * 256];        // [mat][ftile][b] partial sumsq
__device__ float          g_part[B_SZ * 4096];      // [b][k*8 + slot]

// ===========================================================================
// Stage 1: raw maps + partial norms. 512 blocks x 256 thr.
// block = (mat, btile(8 rows), ftile(64 features)); warp w -> 8 features.
// ===========================================================================
__global__ void __launch_bounds__(256) map_kernel(
    const float* __restrict__ img_e, const float* __restrict__ txt_e,
    const float* __restrict__ Wi, const float* __restrict__ bi,
    const float* __restrict__ Wt, const float* __restrict__ bt)
{
    const int bid   = blockIdx.x;
    const int mat   = bid >> 8;
    const int btile = (bid & 255) >> 3;
    const int ftile = bid & 7;
    const float* X    = mat ? txt_e : img_e;
    const float* W    = mat ? Wt : Wi;
    const float* bias = mat ? bt : bi;
    const int b0 = btile * 8;

    __shared__ float xs[8 * 512];
    __shared__ float red[8][8];
    const int tid = threadIdx.x;

    {
        const float4* src = (const float4*)(X + (size_t)b0 * 512);
        float4* xd = (float4*)xs;
        #pragma unroll
        for (int v = tid; v < 1024; v += 256) xd[v] = src[v];
    }
    __syncthreads();

    const int w = tid >> 5, lane = tid & 31;
    const int fbase = ftile * 64 + w * 8;

    float acc[8][8];
    #pragma unroll
    for (int f = 0; f < 8; f++)
        #pragma unroll
        for (int r = 0; r < 8; r++) acc[f][r] = 0.f;

    const float4* xs4 = (const float4*)xs;
    #pragma unroll
    for (int q = 0; q < 4; q++) {
        const int jj = lane + 32 * q;
        float4 xv[8];
        #pragma unroll
        for (int r = 0; r < 8; r++) xv[r] = xs4[r * 128 + jj];
        #pragma unroll
        for (int f = 0; f < 8; f++) {
            float4 wv = ((const float4*)(W + (size_t)(fbase + f) * 512))[jj];
            #pragma unroll
            for (int r = 0; r < 8; r++) {
                acc[f][r] += wv.x * xv[r].x;
                acc[f][r] += wv.y * xv[r].y;
                acc[f][r] += wv.z * xv[r].z;
                acc[f][r] += wv.w * xv[r].w;
            }
        }
    }

    float sq = 0.f;   // lane r accumulates sumsq of row r over this warp's 8 features
    #pragma unroll
    for (int f = 0; f < 8; f++) {
        const float bv = bias[fbase + f];
        #pragma unroll
        for (int r = 0; r < 8; r++) {
            float v = acc[f][r];
            #pragma unroll
            for (int o = 16; o; o >>= 1) v += __shfl_xor_sync(0xFFFFFFFFu, v, o);
            if (lane == r) {
                float y = v + bv;
                if (mat == 0) g_img[(size_t)(b0 + r) * 512 + fbase + f] = y;
                else          g_txt_bf[(size_t)(b0 + r) * 512 + fbase + f] = __float2bfloat16(y);
                sq += y * y;
            }
        }
    }
    if (lane < 8) red[w][lane] = sq;
    __syncthreads();
    if (tid < 8) {
        float s = 0.f;
        #pragma unroll
        for (int ww = 0; ww < 8; ww++) s += red[ww][tid];
        g_n2[mat * 2048 + ftile * 256 + b0 + tid] = s;
    }
}

// ===========================================================================
// Stage 2: bf16 mma.sync bilinear GEMM, 4-stage cp.async multistage.
// CTA: k = bid>>2, ichunk = bid&3. Tile M=256(batch) x N=128(i), K=512(j).
// 256 thr = 8 warps: wm = w>>1 (64 batch rows), wn = w&1 (64 i cols).
// txt bf16 in smem (80B rows, ldmatrix); Wp fp32 in smem (160B rows,
// LDS.64 + cvt -> B fragments; 160B stride is conflict-free per 16-lane phase).
// ===========================================================================

__device__ __forceinline__ uint32_t smem_u32(const void* p) {
    uint32_t a;
    asm("{ .reg .u64 t; cvta.to.shared.u64 t, %1; cvt.u32.u64 %0, t; }"
        : "=r"(a) : "l"(p));
    return a;
}
__device__ __forceinline__ void cp16(uint32_t dst, const void* src) {
    asm volatile("cp.async.cg.shared.global [%0], [%1], 16;" :: "r"(dst), "l"(src));
}
__device__ __forceinline__ void ldsm4(uint32_t& r0, uint32_t& r1,
                                      uint32_t& r2, uint32_t& r3, uint32_t addr) {
    asm volatile("ldmatrix.sync.aligned.m8n8.x4.shared.b16 {%0,%1,%2,%3}, [%4];"
                 : "=r"(r0), "=r"(r1), "=r"(r2), "=r"(r3) : "r"(addr));
}

#define TXT_STG 20480               // 256 rows * 80 B (bf16)
#define WP_STG  20480               // 128 rows * 160 B (fp32)
#define K2_SMEM (4 * (TXT_STG + WP_STG))   // 163840

__global__ void __launch_bounds__(256, 1) bilinear_kernel(const float* __restrict__ Wp)
{
    extern __shared__ __align__(16) char dsm[];
    const uint32_t smb = smem_u32(dsm);

    const int tid  = threadIdx.x;
    const int lane = tid & 31;
    const int w    = tid >> 5;
    const int wm   = w >> 1;       // 0..3 -> batch rows wm*64
    const int wn   = w & 1;        // 0..1 -> i cols wn*64
    const int g    = lane >> 2;    // 0..7
    const int c    = lane & 3;     // 0..3

    const int k      = blockIdx.x >> 2;
    const int ichunk = blockIdx.x & 3;
    const float* wpk = Wp + ((size_t)k << 18) + ((size_t)ichunk << 16);

    // ---- async stage load: txt (bf16) + Wp (fp32), one commit group ----
    auto cp_stage = [&](int jc, int s) {
        const uint32_t tb = smb + s * TXT_STG;
        const uint32_t wb = smb + 4 * TXT_STG + s * WP_STG;
        #pragma unroll
        for (int q = 0; q < 4; q++) {          // txt: 1024 x 16B
            int idx = tid + 256 * q;
            int row = idx >> 2, c16 = idx & 3;
            cp16(tb + (uint32_t)(row * 80 + c16 * 16),
                 g_txt_bf + (size_t)row * 512 + jc * 32 + c16 * 8);
        }
        #pragma unroll
        for (int q = 0; q < 4; q++) {          // wp: 1024 x 16B
            int idx = tid + 256 * q;
            int row = idx >> 3, c16 = idx & 7;
            cp16(wb + (uint32_t)(row * 160 + c16 * 16),
                 wpk + (size_t)row * 512 + jc * 32 + c16 * 4);
        }
        asm volatile("cp.async.commit_group;" ::: "memory");
    };

    // ---- A (txt) ldmatrix lane offsets (proven mapping) ----
    const int ln = lane & 7, sel = lane >> 3;
    const int a_row = ((sel & 1) << 3) + ln, a_half = sel >> 1;
    uint32_t a_off[4];
    #pragma unroll
    for (int mt = 0; mt < 4; mt++)
        a_off[mt] = (uint32_t)((wm * 64 + mt * 16 + a_row) * 80 + a_half * 16);

    float d[4][8][4];
    #pragma unroll
    for (int mt = 0; mt < 4; mt++)
        #pragma unroll
        for (int nt = 0; nt < 8; nt++)
            #pragma unroll
            for (int r = 0; r < 4; r++) d[mt][nt][r] = 0.f;

    cp_stage(0, 0);
    cp_stage(1, 1);
    cp_stage(2, 2);

    #pragma unroll 1
    for (int jc = 0; jc < 16; ++jc) {
        const int s = jc & 3;
        if (jc <= 13)      asm volatile("cp.async.wait_group 2;" ::: "memory");
        else if (jc == 14) asm volatile("cp.async.wait_group 1;" ::: "memory");
        else               asm volatile("cp.async.wait_group 0;" ::: "memory");
        __syncthreads();
        if (jc + 3 < 16) cp_stage(jc + 3, (jc + 3) & 3);

        const uint32_t tb = smb + s * TXT_STG;
        const float* wrow = (const float*)(dsm + 4 * TXT_STG + s * WP_STG)
                            + (wn * 64 + g) * 40 + 2 * c;

        #pragma unroll
        for (int kf = 0; kf < 2; kf++) {
            uint32_t a[4][4];
            #pragma unroll
            for (int mt = 0; mt < 4; mt++)
                ldsm4(a[mt][0], a[mt][1], a[mt][2], a[mt][3],
                      tb + a_off[mt] + kf * 32);

            uint32_t bfr[8][2];
            #pragma unroll
            for (int nt = 0; nt < 8; nt++) {
                const float* p = wrow + nt * 8 * 40 + kf * 16;
                float2 v0 = *(const float2*)p;
                float2 v1 = *(const float2*)(p + 8);
                asm("cvt.rn.bf16x2.f32 %0, %1, %2;" : "=r"(bfr[nt][0]) : "f"(v0.y), "f"(v0.x));
                asm("cvt.rn.bf16x2.f32 %0, %1, %2;" : "=r"(bfr[nt][1]) : "f"(v1.y), "f"(v1.x));
            }
            #pragma unroll
            for (int mt = 0; mt < 4; mt++)
                #pragma unroll
                for (int nt = 0; nt < 8; nt++) {
                    asm volatile(
                        "mma.sync.aligned.m16n8k16.row.col.f32.bf16.bf16.f32 "
                        "{%0,%1,%2,%3},{%4,%5,%6,%7},{%8,%9},{%0,%1,%2,%3};"
                        : "+f"(d[mt][nt][0]), "+f"(d[mt][nt][1]),
                          "+f"(d[mt][nt][2]), "+f"(d[mt][nt][3])
                        : "r"(a[mt][0]), "r"(a[mt][1]), "r"(a[mt][2]), "r"(a[mt][3]),
                          "r"(bfr[nt][0]), "r"(bfr[nt][1]));
                }
        }
    }

    // ---- epilogue: raw feats partial = sum_i img[b,i] * D[b,i] ----
    const int slot = ichunk * 2 + wn;
    #pragma unroll
    for (int mt = 0; mt < 4; mt++) {
        const int b_lo = wm * 64 + mt * 16 + g;
        const int b_hi = b_lo + 8;
        float plo = 0.f, phi = 0.f;
        #pragma unroll
        for (int nt = 0; nt < 8; nt++) {
            const int icol = ichunk * 128 + wn * 64 + nt * 8 + 2 * c;
            float2 vlo = *(const float2*)&g_img[((size_t)b_lo << 9) + icol];
            float2 vhi = *(const float2*)&g_img[((size_t)b_hi << 9) + icol];
            plo += d[mt][nt][0] * vlo.x + d[mt][nt][1] * vlo.y;
            phi += d[mt][nt][2] * vhi.x + d[mt][nt][3] * vhi.y;
        }
        plo += __shfl_xor_sync(0xFFFFFFFFu, plo, 1);
        plo += __shfl_xor_sync(0xFFFFFFFFu, plo, 2);
        phi += __shfl_xor_sync(0xFFFFFFFFu, phi, 1);
        phi += __shfl_xor_sync(0xFFFFFFFFu, phi, 2);
        if (c == 0) {
            g_part[((size_t)b_lo << 12) + k * 8 + slot] = plo;
            g_part[((size_t)b_hi << 12) + k * 8 + slot] = phi;
        }
    }
}

// ===========================================================================
// Stage 3: norms + relu + classifier + sigmoid
// ===========================================================================
__global__ void __launch_bounds__(128) head_kernel(
    const float* __restrict__ bp, const float* __restrict__ Wc,
    const float* __restrict__ bc, float* __restrict__ out)
{
    const int b = blockIdx.x;
    const int t = threadIdx.x;

    float ni2 = 0.f, nt2 = 0.f;
    #pragma unroll
    for (int q = 0; q < 8; q++) {
        ni2 += g_n2[q * 256 + b];
        nt2 += g_n2[2048 + q * 256 + b];
    }
    const float S = 1.0f / (fmaxf(sqrtf(ni2), 1e-12f) * fmaxf(sqrtf(nt2), 1e-12f));

    float s = 0.f;
    for (int k = t; k < 512; k += 128) {
        const float4 v0 = *(const float4*)&g_part[((size_t)b << 12) + k * 8];
        const float4 v1 = *(const float4*)&g_part[((size_t)b << 12) + k * 8 + 4];
        float f = S * (v0.x + v0.y + v0.z + v0.w + v1.x + v1.y + v1.z + v1.w) + bp[k];
        s += fmaxf(f, 0.f) * Wc[k];
    }
    #pragma unroll
    for (int o = 16; o; o >>= 1) s += __shfl_xor_sync(0xFFFFFFFFu, s, o);
    __shared__ float red[4];
    if ((t & 31) == 0) red[t >> 5] = s;
    __syncthreads();
    if (t == 0) {
        float tot = red[0] + red[1] + red[2] + red[3] + bc[0];
        out[b] = 1.f / (1.f + expf(-tot));
    }
}

// ===========================================================================
extern "C" void kernel_launch(void* const* d_in, const int* in_sizes, int n_in,
                              void* d_out, int out_size)
{
    const float* img_e = (const float*)d_in[0];
    const float* txt_e = (const float*)d_in[1];
    const float* Wi    = (const float*)d_in[2];
    const float* bi    = (const float*)d_in[3];
    const float* Wt    = (const float*)d_in[4];
    const float* bt    = (const float*)d_in[5];
    const float* Wp    = (const float*)d_in[6];
    const float* bp    = (const float*)d_in[7];
    const float* Wc    = (const float*)d_in[8];
    const float* bc    = (const float*)d_in[9];
    float* out = (float*)d_out;

    cudaFuncSetAttribute(bilinear_kernel,
                         cudaFuncAttributeMaxDynamicSharedMemorySize, K2_SMEM);

    map_kernel<<<512, 256>>>(img_e, txt_e, Wi, bi, Wt, bt);
    bilinear_kernel<<<2048, 256, K2_SMEM>>>(Wp);
    head_kernel<<<256, 128>>>(bp, Wc, bc, out);
}